// round 10
// baseline (speedup 1.0000x reference)
#include <cuda_runtime.h>
#include <cuda_fp16.h>
#include <cstdint>
#include <math.h>

// ---------------- problem constants ----------------
#define B_    16
#define CIN   512
#define T_    2048
#define H_    2048
#define COUT  512
#define G_    4

// ---------------- tiling ----------------
#define BM 128          // rows per GEMM1 subtile / cout tile
#define BN 128          // t tile
#define BK 32

// ---------------- smem ----------------
// ring: 6 stages x 16KB (A 8KB + B 8KB); h buffer: 512 rows x 256B = 128KB
#define SA    0
#define SB    8192
#define STAGE 16384
#define NSTG  6
#define HOFF  (STAGE * NSTG)                 // 98304
#define SMEM_TOTAL (HOFF + 512 * 256)        // 229376

// A-plane swizzle (64B rows)
__device__ __forceinline__ uint32_t swzb(uint32_t o) {
    return o ^ ((o >> 2) & 0x30) ^ ((o >> 4) & 0x10);
}
__device__ __forceinline__ uint32_t rowsw(int row) {
    return (uint32_t)(((row & 3) << 4) ^ ((row & 4) << 2));
}

// ---------------- device scratch (pre-converted operands) ----------------
__device__ __half g_w1h[(size_t)H_ * 128];
__device__ __half g_w2h[(size_t)COUT * 512];
__device__ __half g_xh[(size_t)B_ * CIN * T_];      // x*mask, fp16

// ---------------- PTX helpers ----------------
__device__ __forceinline__ uint32_t smem_to_u32(const void* p) {
    uint32_t a;
    asm("{ .reg .u64 t; cvta.to.shared.u64 t, %1; cvt.u32.u64 %0, t; }" : "=r"(a) : "l"(p));
    return a;
}
__device__ __forceinline__ void ldsm4(uint32_t* r, uint32_t addr) {
    asm volatile("ldmatrix.sync.aligned.m8n8.x4.shared.b16 {%0,%1,%2,%3}, [%4];"
        : "=r"(r[0]), "=r"(r[1]), "=r"(r[2]), "=r"(r[3]) : "r"(addr));
}
__device__ __forceinline__ void ldsm4t(uint32_t* r, uint32_t addr) {
    asm volatile("ldmatrix.sync.aligned.m8n8.x4.trans.shared.b16 {%0,%1,%2,%3}, [%4];"
        : "=r"(r[0]), "=r"(r[1]), "=r"(r[2]), "=r"(r[3]) : "r"(addr));
}
__device__ __forceinline__ void mma16816(float* c, const uint32_t* a, uint32_t b0, uint32_t b1) {
    asm volatile("mma.sync.aligned.m16n8k16.row.col.f32.f16.f16.f32 "
        "{%0,%1,%2,%3}, {%4,%5,%6,%7}, {%8,%9}, {%0,%1,%2,%3};"
        : "+f"(c[0]), "+f"(c[1]), "+f"(c[2]), "+f"(c[3])
        : "r"(a[0]), "r"(a[1]), "r"(a[2]), "r"(a[3]), "r"(b0), "r"(b1));
}
__device__ __forceinline__ void cpa16(uint32_t dst, const __half* src) {
    asm volatile("cp.async.cg.shared.global [%0], [%1], 16;"
        :: "r"(dst), "l"(__cvta_generic_to_global(src)));
}
#define CP_COMMIT()  asm volatile("cp.async.commit_group;" ::: "memory")
#define CP_WAIT(n)   asm volatile("cp.async.wait_group %0;" :: "n"(n) : "memory")
#define CP_WAIT_AHEAD(ahead) do { \
    if ((ahead) >= 4)      CP_WAIT(4); \
    else if ((ahead) == 3) CP_WAIT(3); \
    else if ((ahead) == 2) CP_WAIT(2); \
    else if ((ahead) == 1) CP_WAIT(1); \
    else                   CP_WAIT(0); } while (0)

__device__ __forceinline__ float gelu_tanh(float v) {
    float u = v * (0.7978845608028654f + 0.03567740814f * v * v);
    float t;
    asm("tanh.approx.f32 %0, %1;" : "=f"(t) : "f"(u));
    float w = 0.5f * v;
    return fmaf(w, t, w);
}

// ---------------- prologue kernels ----------------
__global__ void prep_w(const float* __restrict__ w1, const float* __restrict__ w2) {
    int i = blockIdx.x * 256 + threadIdx.x;              // 65536 float4s each
    union { __half2 h[2]; uint2 u; } p;
    float4 v = ((const float4*)w1)[i];
    p.h[0] = __float22half2_rn(make_float2(v.x, v.y));
    p.h[1] = __float22half2_rn(make_float2(v.z, v.w));
    ((uint2*)g_w1h)[i] = p.u;
    v = ((const float4*)w2)[i];
    p.h[0] = __float22half2_rn(make_float2(v.x, v.y));
    p.h[1] = __float22half2_rn(make_float2(v.z, v.w));
    ((uint2*)g_w2h)[i] = p.u;
}

__global__ void prep_x(const float* __restrict__ x, const float* __restrict__ xm) {
    size_t i = (size_t)blockIdx.x * 256 + threadIdx.x;   // float4 index
    size_t e = i * 4;
    int t = (int)(e & (T_ - 1));
    int b = (int)(e >> 20);                              // CIN*T_ = 2^20
    float4 v = ((const float4*)x)[i];
    float4 mk = *(const float4*)(xm + (size_t)b * T_ + t);
    v.x *= mk.x; v.y *= mk.y; v.z *= mk.z; v.w *= mk.w;
    union { __half2 h[2]; uint2 u; } p;
    p.h[0] = __float22half2_rn(make_float2(v.x, v.y));
    p.h[1] = __float22half2_rn(make_float2(v.z, v.w));
    ((uint2*)g_xh)[i] = p.u;
}

// ---------------- prefetchers (512 threads: 1 x 16B A, 1 x 16B B each) ----------------
__device__ __forceinline__ void prefetch_s1(uint32_t stg, int c, int g2, int b, int t0, int tid)
{
    int g = c >> 2, kk = c & 3;
    {   // A: w1 rows (g*512 + g2*128) + 128, cols kk*32..+32
        int m = tid >> 2, q = tid & 3;
        const __half* src = g_w1h + (size_t)(g * 512 + g2 * 128 + m) * 128 + kk * 32 + q * 8;
        cpa16(stg + SA + swzb((uint32_t)(m * 64 + q * 16)), src);
    }
    {   // B: x group g, channels kk*32.., 128 t
        int k = tid >> 4, tc = tid & 15;
        const __half* src = g_xh + ((size_t)b * CIN + g * 128 + kk * 32 + k) * T_ + t0 + tc * 8;
        cpa16(stg + SB + (uint32_t)(k * 256) + (((uint32_t)(tc * 16)) ^ ((uint32_t)(k & 7) << 4)), src);
    }
}
__device__ __forceinline__ void prefetch_s2(uint32_t stg, int c, int g2, int tid)
{
    int m = tid >> 2, q = tid & 3;
    const __half* src = g_w2h + (size_t)(g2 * 128 + m) * 512 + c * 32 + q * 8;
    cpa16(stg + SA + swzb((uint32_t)(m * 64 + q * 16)), src);
}

// ---------------- chunk body: 32x32 warp tile, A ring plane, B 256B-row plane ----------------
__device__ __forceinline__ void mma_chunk(float acc[2][4][4], uint32_t aStg, uint32_t bBase,
                                          int wm, int wn, int lid)
{
    const int rA = lid & 15;
    const int cA = (lid >> 4) << 4;
    const int kB = lid & 15;
    const uint32_t nb0 = (uint32_t)(wn * 64 + ((lid >> 4) << 4));   // t-bytes

    #pragma unroll
    for (int k16 = 0; k16 < 2; k16++) {
        uint32_t a[2][4];
        #pragma unroll
        for (int mi = 0; mi < 2; mi++) {
            int row = wm * 32 + mi * 16 + rA;
            uint32_t off = (uint32_t)(row * 64) + (((uint32_t)(k16 * 32 + cA)) ^ rowsw(row));
            ldsm4(a[mi], aStg + SA + off);
        }
        int krow = k16 * 16 + kB;
        uint32_t baddr = bBase + (uint32_t)(krow * 256);
        uint32_t bsw   = ((uint32_t)(krow & 7)) << 4;
        #pragma unroll
        for (int nj = 0; nj < 2; nj++) {
            uint32_t bT[4];
            ldsm4t(bT, baddr + ((nb0 + (uint32_t)(nj * 32)) ^ bsw));
            #pragma unroll
            for (int h = 0; h < 2; h++)
                #pragma unroll
                for (int mi = 0; mi < 2; mi++)
                    mma16816(acc[mi][nj * 2 + h], a[mi], bT[h * 2], bT[h * 2 + 1]);
        }
    }
}

// ---------------- fused kernel ----------------
__global__ __launch_bounds__(512, 1)
void ffn_fused(const float* __restrict__ b1, const float* __restrict__ b2,
               const float* __restrict__ xm, float* __restrict__ out)
{
    extern __shared__ char smem[];
    const uint32_t sb = smem_to_u32(smem);
    const int tid = threadIdx.x, wid = tid >> 5, lid = tid & 31;
    const int wm = wid & 3, wn = wid >> 2;               // 4x4 warps, 32x32 tiles
    const int t0 = blockIdx.x * BN, g2 = blockIdx.y, b = blockIdx.z;
    const int gid = lid >> 2, qid = lid & 3;

    float acc[2][4][4];
    #pragma unroll
    for (int i = 0; i < 2; i++)
        #pragma unroll
        for (int j = 0; j < 4; j++)
            #pragma unroll
            for (int q = 0; q < 4; q++) acc[i][j][q] = 0.f;

    // ===== stage 1: 4 sub-GEMMs (g = 0..3), 16 chunks streamed through the ring =====
    {
        int wstg = 0, rstg = 0;
        #pragma unroll 1
        for (int s = 0; s < 4; s++) {
            prefetch_s1(sb + wstg * STAGE, s, g2, b, t0, tid);
            CP_COMMIT();
            if (++wstg == NSTG) wstg = 0;
        }
        #pragma unroll 1
        for (int c = 0; c < 16; c++) {
            if (c + 4 < 16) {
                prefetch_s1(sb + wstg * STAGE, c + 4, g2, b, t0, tid);
                CP_COMMIT();
                if (++wstg == NSTG) wstg = 0;
            }
            CP_WAIT_AHEAD(15 - c);
            __syncthreads();
            uint32_t stg = sb + rstg * STAGE;
            mma_chunk(acc, stg, stg + SB, wm, wn, lid);
            if (++rstg == NSTG) rstg = 0;

            if ((c & 3) == 3) {
                // sub-GEMM g = c>>2 complete: bias + gelu -> h smem (shuffled rows s=4*jj+g)
                int g = c >> 2;
                #pragma unroll
                for (int mi = 0; mi < 2; mi++) {
                    #pragma unroll
                    for (int half = 0; half < 2; half++) {
                        int jj = wm * 32 + mi * 16 + gid + half * 8;
                        float bias = b1[g * 512 + g2 * 128 + jj];
                        int s = 4 * jj + g;
                        uint32_t rowbase = HOFF + (uint32_t)(s * 256);
                        uint32_t rsw = ((uint32_t)(s & 7)) << 4;
                        #pragma unroll
                        for (int n8 = 0; n8 < 4; n8++) {
                            int tl = wn * 32 + n8 * 8 + qid * 2;
                            float ox = gelu_tanh(acc[mi][n8][half * 2 + 0] + bias);
                            float oy = gelu_tanh(acc[mi][n8][half * 2 + 1] + bias);
                            *(__half2*)(smem + rowbase + (((uint32_t)(tl * 2)) ^ rsw)) =
                                __float22half2_rn(make_float2(ox, oy));
                        }
                    }
                }
                #pragma unroll
                for (int i = 0; i < 2; i++)
                    #pragma unroll
                    for (int j = 0; j < 4; j++)
                        #pragma unroll
                        for (int q = 0; q < 4; q++) acc[i][j][q] = 0.f;
            }
        }
    }
    __syncthreads();      // h complete + ring free

    // ===== stage 2: out tile = W2[g2] @ h (K=512 from smem) =====
    {
        int wstg = 0, rstg = 0;
        #pragma unroll 1
        for (int s = 0; s < 4; s++) {
            prefetch_s2(sb + wstg * STAGE, s, g2, tid);
            CP_COMMIT();
            if (++wstg == NSTG) wstg = 0;
        }
        #pragma unroll 1
        for (int c = 0; c < 16; c++) {
            if (c + 4 < 16) {
                prefetch_s2(sb + wstg * STAGE, c + 4, g2, tid);
                CP_COMMIT();
                if (++wstg == NSTG) wstg = 0;
            }
            CP_WAIT_AHEAD(15 - c);
            __syncthreads();
            mma_chunk(acc, sb + rstg * STAGE, sb + HOFF + (uint32_t)(c * 8192), wm, wn, lid);
            if (++rstg == NSTG) rstg = 0;
        }
    }

    // epilogue: bias + mask -> out
    const float* mrow = xm + (size_t)b * T_ + t0;
    #pragma unroll
    for (int mi = 0; mi < 2; mi++) {
        #pragma unroll
        for (int half = 0; half < 2; half++) {
            int   m    = g2 * 128 + wm * 32 + mi * 16 + gid + half * 8;
            float bias = b2[m];
            float* orow = out + ((size_t)b * COUT + m) * T_ + t0;
            #pragma unroll
            for (int n8 = 0; n8 < 4; n8++) {
                int tl = wn * 32 + n8 * 8 + qid * 2;
                float2 mk = *(const float2*)(mrow + tl);
                float2 o;
                o.x = (acc[mi][n8][half * 2 + 0] + bias) * mk.x;
                o.y = (acc[mi][n8][half * 2 + 1] + bias) * mk.y;
                *(float2*)(orow + tl) = o;
            }
        }
    }
}

// ---------------- launch ----------------
extern "C" void kernel_launch(void* const* d_in, const int* in_sizes, int n_in,
                              void* d_out, int out_size)
{
    const float* x  = (const float*)d_in[0];
    const float* xm = (const float*)d_in[1];
    const float* w1 = (const float*)d_in[2];
    const float* b1 = (const float*)d_in[3];
    const float* w2 = (const float*)d_in[4];
    const float* b2 = (const float*)d_in[5];
    float* out = (float*)d_out;

    cudaFuncSetAttribute(ffn_fused, cudaFuncAttributeMaxDynamicSharedMemorySize, SMEM_TOTAL);

    prep_w<<<256, 256>>>(w1, w2);
    prep_x<<<16384, 256>>>(x, xm);

    dim3 grid(T_ / BN, G_, B_);          // (16, 4, 16) = 1024 CTAs
    ffn_fused<<<grid, 512, SMEM_TOTAL>>>(b1, b2, xm, out);
}

// round 11
// speedup vs baseline: 1.1765x; 1.1765x over previous
#include <cuda_runtime.h>
#include <cuda_fp16.h>
#include <cstdint>
#include <math.h>

// ---------------- problem constants ----------------
#define B_    16
#define CIN   512
#define T_    2048
#define H_    2048
#define COUT  512
#define G_    4

// ---------------- tiling ----------------
#define BM 128
#define BN 128
#define BK 32
#define TT 4               // t-tiles per l1 CTA (weight reuse)

// ---------------- smem ----------------
// l1: A 4 planes x 8KB = 32KB + B ring 6 x 8KB = 48KB -> 80KB (2 CTAs/SM)
// l2: ring 6 x 16KB = 96KB (2 CTAs/SM)  [R9 layout]
#define L1_AB    32768                  // B ring base in l1
#define L1_SMEM  (L1_AB + 6 * 8192)    // 81920
#define SA    0
#define SB    8192
#define STAGE 16384
#define NSTG  6
#define L2_SMEM (STAGE * NSTG)          // 98304

__device__ __forceinline__ uint32_t swzb(uint32_t o) {
    return o ^ ((o >> 2) & 0x30) ^ ((o >> 4) & 0x10);
}
__device__ __forceinline__ uint32_t rowsw(int row) {
    return (uint32_t)(((row & 3) << 4) ^ ((row & 4) << 2));
}

// ---------------- device scratch ----------------
__device__ __half g_w1h[(size_t)H_ * 128];
__device__ __half g_w2h[(size_t)COUT * 512];
__device__ __half g_xh[(size_t)B_ * CIN * T_];
__device__ __half g_h [(size_t)B_ * H_  * T_];

// ---------------- PTX helpers ----------------
__device__ __forceinline__ uint32_t smem_to_u32(const void* p) {
    uint32_t a;
    asm("{ .reg .u64 t; cvta.to.shared.u64 t, %1; cvt.u32.u64 %0, t; }" : "=r"(a) : "l"(p));
    return a;
}
__device__ __forceinline__ void ldsm4(uint32_t* r, uint32_t addr) {
    asm volatile("ldmatrix.sync.aligned.m8n8.x4.shared.b16 {%0,%1,%2,%3}, [%4];"
        : "=r"(r[0]), "=r"(r[1]), "=r"(r[2]), "=r"(r[3]) : "r"(addr));
}
__device__ __forceinline__ void ldsm4t(uint32_t* r, uint32_t addr) {
    asm volatile("ldmatrix.sync.aligned.m8n8.x4.trans.shared.b16 {%0,%1,%2,%3}, [%4];"
        : "=r"(r[0]), "=r"(r[1]), "=r"(r[2]), "=r"(r[3]) : "r"(addr));
}
__device__ __forceinline__ void mma16816(float* c, const uint32_t* a, uint32_t b0, uint32_t b1) {
    asm volatile("mma.sync.aligned.m16n8k16.row.col.f32.f16.f16.f32 "
        "{%0,%1,%2,%3}, {%4,%5,%6,%7}, {%8,%9}, {%0,%1,%2,%3};"
        : "+f"(c[0]), "+f"(c[1]), "+f"(c[2]), "+f"(c[3])
        : "r"(a[0]), "r"(a[1]), "r"(a[2]), "r"(a[3]), "r"(b0), "r"(b1));
}
__device__ __forceinline__ void cpa16(uint32_t dst, const __half* src) {
    asm volatile("cp.async.cg.shared.global [%0], [%1], 16;"
        :: "r"(dst), "l"(__cvta_generic_to_global(src)));
}
#define CP_COMMIT()  asm volatile("cp.async.commit_group;" ::: "memory")
#define CP_WAIT(n)   asm volatile("cp.async.wait_group %0;" :: "n"(n) : "memory")
#define CP_WAIT_AHEAD(ahead) do { \
    if ((ahead) >= 4)      CP_WAIT(4); \
    else if ((ahead) == 3) CP_WAIT(3); \
    else if ((ahead) == 2) CP_WAIT(2); \
    else if ((ahead) == 1) CP_WAIT(1); \
    else                   CP_WAIT(0); } while (0)

__device__ __forceinline__ float gelu_tanh(float v) {
    float u = v * (0.7978845608028654f + 0.03567740814f * v * v);
    float t;
    asm("tanh.approx.f32 %0, %1;" : "=f"(t) : "f"(u));
    float w = 0.5f * v;
    return fmaf(w, t, w);
}

// ---------------- prologue kernels ----------------
__global__ void prep_w(const float* __restrict__ w1, const float* __restrict__ w2) {
    int i = blockIdx.x * 256 + threadIdx.x;
    union { __half2 h[2]; uint2 u; } p;
    float4 v = ((const float4*)w1)[i];
    p.h[0] = __float22half2_rn(make_float2(v.x, v.y));
    p.h[1] = __float22half2_rn(make_float2(v.z, v.w));
    ((uint2*)g_w1h)[i] = p.u;
    v = ((const float4*)w2)[i];
    p.h[0] = __float22half2_rn(make_float2(v.x, v.y));
    p.h[1] = __float22half2_rn(make_float2(v.z, v.w));
    ((uint2*)g_w2h)[i] = p.u;
}

__global__ void prep_x(const float* __restrict__ x, const float* __restrict__ xm) {
    size_t i = (size_t)blockIdx.x * 256 + threadIdx.x;
    size_t e = i * 4;
    int t = (int)(e & (T_ - 1));
    int b = (int)(e >> 20);
    float4 v = ((const float4*)x)[i];
    float4 mk = *(const float4*)(xm + (size_t)b * T_ + t);
    v.x *= mk.x; v.y *= mk.y; v.z *= mk.z; v.w *= mk.w;
    union { __half2 h[2]; uint2 u; } p;
    p.h[0] = __float22half2_rn(make_float2(v.x, v.y));
    p.h[1] = __float22half2_rn(make_float2(v.z, v.w));
    ((uint2*)g_xh)[i] = p.u;
}

// ---------------- mainloop body: one BK=32 chunk (8 warps, 32x64 warp tiles) ----------------
__device__ __forceinline__ void mma_chunk1(float acc[2][8][4], uint32_t aBase, uint32_t bBase,
                                           int warp_m, int warp_n, int lid)
{
    const int rA = lid & 15;
    const int cA = (lid >> 4) << 4;
    const int kB = lid & 15;
    const uint32_t nbyte = (uint32_t)(warp_n * 128 + ((lid >> 4) << 4));

    #pragma unroll
    for (int k16 = 0; k16 < 2; k16++) {
        uint32_t aH[2][4];
        #pragma unroll
        for (int mi = 0; mi < 2; mi++) {
            int row = warp_m * 32 + mi * 16 + rA;
            uint32_t off = (uint32_t)(row * 64) + (((uint32_t)(k16 * 32 + cA)) ^ rowsw(row));
            ldsm4(aH[mi], aBase + off);
        }
        int krow = k16 * 16 + kB;
        uint32_t baddr = bBase + (uint32_t)(krow * 256);
        uint32_t bsw   = ((uint32_t)(krow & 7)) << 4;
        #pragma unroll
        for (int nj = 0; nj < 4; nj++) {
            uint32_t bT[4];
            ldsm4t(bT, baddr + ((nbyte + (uint32_t)(nj * 32)) ^ bsw));
            #pragma unroll
            for (int h = 0; h < 2; h++)
                #pragma unroll
                for (int mi = 0; mi < 2; mi++)
                    mma16816(acc[mi][nj * 2 + h], aH[mi], bT[h * 2], bT[h * 2 + 1]);
        }
    }
}

// ---------------- layer 1: per-CTA weight-tile reuse over TT=4 t-tiles ----------------
__global__ __launch_bounds__(256, 2)
void ffn_l1(const float* __restrict__ b1)
{
    extern __shared__ char smem[];
    const uint32_t sb = smem_to_u32(smem);
    const int tid = threadIdx.x, wid = tid >> 5, lid = tid & 31;
    const int warp_m = wid >> 1, warp_n = wid & 1;
    const int tb = blockIdx.x * TT;                      // first t-tile index
    const int m0 = blockIdx.y * BM, b = blockIdx.z;
    const int g = m0 >> 9;

    const __half* Ag = g_w1h + (size_t)m0 * 128;
    const __half* Bg0 = g_xh + ((size_t)b * CIN + g * 128) * T_;

    float acc[2][8][4];
    #pragma unroll
    for (int i = 0; i < 2; i++)
        #pragma unroll
        for (int j = 0; j < 8; j++)
            #pragma unroll
            for (int q = 0; q < 4; q++) acc[i][j][q] = 0.f;

    // group0: full A (4 planes) + B chunk 0
    {
        #pragma unroll
        for (int it = 0; it < 8; it++) {                 // 2048 x 16B
            int idx = it * 256 + tid;
            int kk = idx >> 9, r = (idx & 511) >> 2, q = idx & 3;
            cpa16(sb + (uint32_t)(kk * 8192) + swzb((uint32_t)(r * 64 + q * 16)),
                  Ag + (size_t)r * 128 + kk * 32 + q * 8);
        }
    }
    // B chunk cc: tile = cc>>2, kk = cc&3
    auto bsrc = [&](int cc, int idx) -> const __half* {
        int k = idx >> 4, tc = idx & 15;
        int t0 = (tb + (cc >> 2)) * BN;
        return Bg0 + (size_t)((cc & 3) * 32 + k) * T_ + t0 + tc * 8;
    };
    {
        #pragma unroll
        for (int it = 0; it < 2; it++) {
            int idx = it * 256 + tid;
            int k = idx >> 4, tc = idx & 15;
            cpa16(sb + L1_AB + (uint32_t)(k * 256) + (((uint32_t)(tc * 16)) ^ ((uint32_t)(k & 7) << 4)),
                  bsrc(0, idx));
        }
        CP_COMMIT();
    }
    #pragma unroll 1
    for (int s = 1; s < 4; s++) {
        #pragma unroll
        for (int it = 0; it < 2; it++) {
            int idx = it * 256 + tid;
            int k = idx >> 4, tc = idx & 15;
            cpa16(sb + L1_AB + (uint32_t)(s * 8192) + (uint32_t)(k * 256) +
                      (((uint32_t)(tc * 16)) ^ ((uint32_t)(k & 7) << 4)),
                  bsrc(s, idx));
        }
        CP_COMMIT();
    }

    const int gid = lid >> 2, qid = lid & 3;
    int wstg = 4, rstg = 0;
    #pragma unroll 1
    for (int c = 0; c < 4 * TT; c++) {
        if (c + 4 < 4 * TT) {
            #pragma unroll
            for (int it = 0; it < 2; it++) {
                int idx = it * 256 + tid;
                int k = idx >> 4, tc = idx & 15;
                cpa16(sb + L1_AB + (uint32_t)(wstg * 8192) + (uint32_t)(k * 256) +
                          (((uint32_t)(tc * 16)) ^ ((uint32_t)(k & 7) << 4)),
                      bsrc(c + 4, idx));
            }
            CP_COMMIT();
            if (++wstg == NSTG) wstg = 0;
        }
        CP_WAIT_AHEAD(4 * TT - 1 - c);
        __syncthreads();
        mma_chunk1(acc, sb + (uint32_t)((c & 3) * 8192), sb + L1_AB + (uint32_t)(rstg * 8192),
                   warp_m, warp_n, lid);
        if (++rstg == NSTG) rstg = 0;

        if ((c & 3) == 3) {
            // tile (c>>2) done: bias + gelu -> fp16, channel-shuffled store
            int t0 = (tb + (c >> 2)) * BN;
            #pragma unroll
            for (int mi = 0; mi < 2; mi++) {
                #pragma unroll
                for (int half = 0; half < 2; half++) {
                    int   m    = m0 + warp_m * 32 + mi * 16 + gid + half * 8;
                    float bias = b1[m];
                    int   cs   = ((m & 511) << 2) + g;
                    __half* orow = g_h + ((size_t)b * H_ + cs) * T_ + t0 + warp_n * 64;
                    #pragma unroll
                    for (int nj8 = 0; nj8 < 8; nj8++) {
                        float ox = gelu_tanh(acc[mi][nj8][half * 2 + 0] + bias);
                        float oy = gelu_tanh(acc[mi][nj8][half * 2 + 1] + bias);
                        *(__half2*)(orow + nj8 * 8 + qid * 2) = __float22half2_rn(make_float2(ox, oy));
                    }
                }
            }
            #pragma unroll
            for (int i = 0; i < 2; i++)
                #pragma unroll
                for (int j = 0; j < 8; j++)
                    #pragma unroll
                    for (int q = 0; q < 4; q++) acc[i][j][q] = 0.f;
        }
    }
}

// ---------------- layer 2: out = (W2 @ g_h + b2) * mask  [R9 verbatim] ----------------
__device__ __forceinline__ void prefetch2(uint32_t stg, const __half* Ag,
                                          const __half* Bg, int ldk, int tid)
{
    #pragma unroll
    for (int it = 0; it < 2; it++) {
        int idx = it * 256 + tid;
        int m = idx >> 2, q = idx & 3;
        cpa16(stg + SA + swzb((uint32_t)(m * 64 + q * 16)), Ag + (size_t)m * ldk + q * 8);
    }
    #pragma unroll
    for (int it = 0; it < 2; it++) {
        int idx = it * 256 + tid;
        int k = idx >> 4, tc = idx & 15;
        cpa16(stg + SB + (uint32_t)(k * 256) + (((uint32_t)(tc * 16)) ^ ((uint32_t)(k & 7) << 4)),
              Bg + (size_t)k * T_ + tc * 8);
    }
}

__global__ __launch_bounds__(256, 2)
void ffn_l2(const float* __restrict__ xm, const float* __restrict__ b2,
            float* __restrict__ out)
{
    extern __shared__ char smem[];
    const uint32_t sb = smem_to_u32(smem);
    const int tid = threadIdx.x, wid = tid >> 5, lid = tid & 31;
    const int warp_m = wid >> 1, warp_n = wid & 1;
    const int t0 = blockIdx.x * BN, m0 = blockIdx.y * BM, b = blockIdx.z;
    const int g2 = blockIdx.y;

    const __half* Ag = g_w2h + (size_t)m0 * 512;
    const __half* Bg = g_h + ((size_t)b * H_ + g2 * 512) * T_ + t0;
    const float* mrow = xm + (size_t)b * T_ + t0;

    float acc[2][8][4];
    #pragma unroll
    for (int i = 0; i < 2; i++)
        #pragma unroll
        for (int j = 0; j < 8; j++)
            #pragma unroll
            for (int q = 0; q < 4; q++) acc[i][j][q] = 0.f;

    int wstg = 0;
    for (int s = 0; s < 4; s++) {
        prefetch2(sb + wstg * STAGE, Ag + s * BK, Bg + (size_t)(s * BK) * T_, 512, tid);
        CP_COMMIT();
        if (++wstg == NSTG) wstg = 0;
    }
    int rstg = 0;
    #pragma unroll 1
    for (int c = 0; c < 16; c++) {
        if (c + 4 < 16) {
            prefetch2(sb + wstg * STAGE, Ag + (c + 4) * BK,
                      Bg + (size_t)((c + 4) * BK) * T_, 512, tid);
            CP_COMMIT();
            if (++wstg == NSTG) wstg = 0;
        }
        CP_WAIT_AHEAD(15 - c);
        __syncthreads();
        mma_chunk1(acc, sb + rstg * STAGE + SA, sb + rstg * STAGE + SB, warp_m, warp_n, lid);
        if (++rstg == NSTG) rstg = 0;
    }

    const int gid = lid >> 2, qid = lid & 3;
    #pragma unroll
    for (int mi = 0; mi < 2; mi++) {
        #pragma unroll
        for (int half = 0; half < 2; half++) {
            int   m    = m0 + warp_m * 32 + mi * 16 + gid + half * 8;
            float bias = b2[m];
            float* orow = out + ((size_t)b * COUT + m) * T_ + t0 + warp_n * 64;
            const float* mr = mrow + warp_n * 64;
            #pragma unroll
            for (int nj8 = 0; nj8 < 8; nj8++) {
                float2 mk = *(const float2*)(mr + nj8 * 8 + qid * 2);
                float2 o;
                o.x = (acc[mi][nj8][half * 2 + 0] + bias) * mk.x;
                o.y = (acc[mi][nj8][half * 2 + 1] + bias) * mk.y;
                *(float2*)(orow + nj8 * 8 + qid * 2) = o;
            }
        }
    }
}

// ---------------- launch ----------------
extern "C" void kernel_launch(void* const* d_in, const int* in_sizes, int n_in,
                              void* d_out, int out_size)
{
    const float* x  = (const float*)d_in[0];
    const float* xm = (const float*)d_in[1];
    const float* w1 = (const float*)d_in[2];
    const float* b1 = (const float*)d_in[3];
    const float* w2 = (const float*)d_in[4];
    const float* b2 = (const float*)d_in[5];
    float* out = (float*)d_out;

    cudaFuncSetAttribute(ffn_l1, cudaFuncAttributeMaxDynamicSharedMemorySize, L1_SMEM);
    cudaFuncSetAttribute(ffn_l2, cudaFuncAttributeMaxDynamicSharedMemorySize, L2_SMEM);

    prep_w<<<256, 256>>>(w1, w2);
    prep_x<<<16384, 256>>>(x, xm);

    dim3 g1(T_ / BN / TT, H_ / BM, B_);  // (4, 16, 16) = 1024 CTAs
    ffn_l1<<<g1, 256, L1_SMEM>>>(b1);

    dim3 g2(T_ / BN, COUT / BM, B_);     // (16, 4, 16) = 1024 CTAs
    ffn_l2<<<g2, 256, L2_SMEM>>>(xm, b2, out);
}

// round 13
// speedup vs baseline: 1.2098x; 1.0283x over previous
#include <cuda_runtime.h>
#include <cuda_fp16.h>
#include <cstdint>
#include <math.h>

// ---------------- problem constants ----------------
#define B_    16
#define CIN   512
#define T_    2048
#define H_    2048
#define COUT  512
#define G_    4

// ---------------- tiling ----------------
#define BM 128
#define BN 128
#define BK 32
#define TT 4               // t-tiles per l1 CTA (weight reuse)

// ---------------- smem ----------------
#define L1_AB    32768                  // l1: A 4 planes (32KB) then B ring 6 x 8KB
#define L1_SMEM  (L1_AB + 6 * 8192)     // 81920  -> 2 CTAs/SM
#define SA    0
#define SB    8192
#define STAGE 16384
#define NSTG  6
#define L2_SMEM (STAGE * NSTG)          // 98304  -> 2 CTAs/SM

__device__ __forceinline__ uint32_t swzb(uint32_t o) {
    return o ^ ((o >> 2) & 0x30) ^ ((o >> 4) & 0x10);
}
__device__ __forceinline__ uint32_t rowsw(int row) {
    return (uint32_t)(((row & 3) << 4) ^ ((row & 4) << 2));
}

// ---------------- device scratch ----------------
__device__ __half g_w1h[(size_t)H_ * 128];
__device__ __half g_w2h[(size_t)COUT * 512];
__device__ __half g_xh[(size_t)B_ * CIN * T_];
__device__ __half g_h [(size_t)B_ * H_  * T_];

// ---------------- PTX helpers ----------------
__device__ __forceinline__ uint32_t smem_to_u32(const void* p) {
    uint32_t a;
    asm("{ .reg .u64 t; cvta.to.shared.u64 t, %1; cvt.u32.u64 %0, t; }" : "=r"(a) : "l"(p));
    return a;
}
__device__ __forceinline__ void ldsm4(uint32_t* r, uint32_t addr) {
    asm volatile("ldmatrix.sync.aligned.m8n8.x4.shared.b16 {%0,%1,%2,%3}, [%4];"
        : "=r"(r[0]), "=r"(r[1]), "=r"(r[2]), "=r"(r[3]) : "r"(addr));
}
__device__ __forceinline__ void ldsm4t(uint32_t* r, uint32_t addr) {
    asm volatile("ldmatrix.sync.aligned.m8n8.x4.trans.shared.b16 {%0,%1,%2,%3}, [%4];"
        : "=r"(r[0]), "=r"(r[1]), "=r"(r[2]), "=r"(r[3]) : "r"(addr));
}
__device__ __forceinline__ void mma16816(float* c, const uint32_t* a, uint32_t b0, uint32_t b1) {
    asm volatile("mma.sync.aligned.m16n8k16.row.col.f32.f16.f16.f32 "
        "{%0,%1,%2,%3}, {%4,%5,%6,%7}, {%8,%9}, {%0,%1,%2,%3};"
        : "+f"(c[0]), "+f"(c[1]), "+f"(c[2]), "+f"(c[3])
        : "r"(a[0]), "r"(a[1]), "r"(a[2]), "r"(a[3]), "r"(b0), "r"(b1));
}
__device__ __forceinline__ void cpa16(uint32_t dst, const __half* src) {
    asm volatile("cp.async.cg.shared.global [%0], [%1], 16;"
        :: "r"(dst), "l"(__cvta_generic_to_global(src)));
}
#define CP_COMMIT()  asm volatile("cp.async.commit_group;" ::: "memory")
#define CP_WAIT(n)   asm volatile("cp.async.wait_group %0;" :: "n"(n) : "memory")

__device__ __forceinline__ float gelu_tanh(float v) {
    float u = v * (0.7978845608028654f + 0.03567740814f * v * v);
    float t;
    asm("tanh.approx.f32 %0, %1;" : "=f"(t) : "f"(u));
    float w = 0.5f * v;
    return fmaf(w, t, w);
}

// ---------------- single prologue kernel: x*mask->fp16 and w1/w2->fp16 ----------------
__global__ void prep_all(const float* __restrict__ x, const float* __restrict__ xm,
                         const float* __restrict__ w1, const float* __restrict__ w2)
{
    int bid = blockIdx.x;
    union { __half2 h[2]; uint2 u; } p;
    if (bid < 16384) {
        size_t i = (size_t)bid * 256 + threadIdx.x;       // float4 index into x
        size_t e = i * 4;
        int t = (int)(e & (T_ - 1));
        int b = (int)(e >> 20);                           // CIN*T_ = 2^20
        float4 v = ((const float4*)x)[i];
        float4 mk = *(const float4*)(xm + (size_t)b * T_ + t);
        v.x *= mk.x; v.y *= mk.y; v.z *= mk.z; v.w *= mk.w;
        p.h[0] = __float22half2_rn(make_float2(v.x, v.y));
        p.h[1] = __float22half2_rn(make_float2(v.z, v.w));
        ((uint2*)g_xh)[i] = p.u;
    } else {
        int i = (bid - 16384) * 256 + threadIdx.x;        // 65536 float4s each tensor
        float4 v = ((const float4*)w1)[i];
        p.h[0] = __float22half2_rn(make_float2(v.x, v.y));
        p.h[1] = __float22half2_rn(make_float2(v.z, v.w));
        ((uint2*)g_w1h)[i] = p.u;
        v = ((const float4*)w2)[i];
        p.h[0] = __float22half2_rn(make_float2(v.x, v.y));
        p.h[1] = __float22half2_rn(make_float2(v.z, v.w));
        ((uint2*)g_w2h)[i] = p.u;
    }
}

// ---------------- mainloop body: one BK=32 chunk (8 warps, 32x64 warp tiles) ----------------
__device__ __forceinline__ void mma_chunk1(float acc[2][8][4], uint32_t aBase, uint32_t bBase,
                                           int warp_m, int warp_n, int lid)
{
    const int rA = lid & 15;
    const int cA = (lid >> 4) << 4;
    const int kB = lid & 15;
    const uint32_t nbyte = (uint32_t)(warp_n * 128 + ((lid >> 4) << 4));

    #pragma unroll
    for (int k16 = 0; k16 < 2; k16++) {
        uint32_t aH[2][4];
        #pragma unroll
        for (int mi = 0; mi < 2; mi++) {
            int row = warp_m * 32 + mi * 16 + rA;
            uint32_t off = (uint32_t)(row * 64) + (((uint32_t)(k16 * 32 + cA)) ^ rowsw(row));
            ldsm4(aH[mi], aBase + off);
        }
        int krow = k16 * 16 + kB;
        uint32_t baddr = bBase + (uint32_t)(krow * 256);
        uint32_t bsw   = ((uint32_t)(krow & 7)) << 4;
        #pragma unroll
        for (int nj = 0; nj < 4; nj++) {
            uint32_t bT[4];
            ldsm4t(bT, baddr + ((nbyte + (uint32_t)(nj * 32)) ^ bsw));
            #pragma unroll
            for (int h = 0; h < 2; h++)
                #pragma unroll
                for (int mi = 0; mi < 2; mi++)
                    mma16816(acc[mi][nj * 2 + h], aH[mi], bT[h * 2], bT[h * 2 + 1]);
        }
    }
}

// ---------------- layer 1: weight-tile reuse over TT=4 t-tiles, pair-synced ----------------
__global__ __launch_bounds__(256, 2)
void ffn_l1(const float* __restrict__ b1)
{
    extern __shared__ char smem[];
    const uint32_t sb = smem_to_u32(smem);
    const int tid = threadIdx.x, wid = tid >> 5, lid = tid & 31;
    const int warp_m = wid >> 1, warp_n = wid & 1;
    const int tb = blockIdx.x * TT;
    const int m0 = blockIdx.y * BM, b = blockIdx.z;
    const int g = m0 >> 9;

    const __half* Ag = g_w1h + (size_t)m0 * 128;
    const __half* Bg0 = g_xh + ((size_t)b * CIN + g * 128) * T_;

    float acc[2][8][4];
    #pragma unroll
    for (int i = 0; i < 2; i++)
        #pragma unroll
        for (int j = 0; j < 8; j++)
            #pragma unroll
            for (int q = 0; q < 4; q++) acc[i][j][q] = 0.f;

    // preload all 4 A planes (folded into the stage-0 commit group)
    #pragma unroll
    for (int it = 0; it < 8; it++) {
        int idx = it * 256 + tid;
        int kk = idx >> 9, r = (idx & 511) >> 2, q = idx & 3;
        cpa16(sb + (uint32_t)(kk * 8192) + swzb((uint32_t)(r * 64 + q * 16)),
              Ag + (size_t)r * 128 + kk * 32 + q * 8);
    }
    // B chunk cc: tile = cc>>2, kk = cc&3
    auto bfill = [&sb, &tb, &Bg0, &tid](int stg, int cc) {
        #pragma unroll
        for (int it = 0; it < 2; it++) {
            int idx = it * 256 + tid;
            int k = idx >> 4, tc = idx & 15;
            int t0 = (tb + (cc >> 2)) * BN;
            cpa16(sb + L1_AB + (uint32_t)(stg * 8192) + (uint32_t)(k * 256) +
                      (((uint32_t)(tc * 16)) ^ ((uint32_t)(k & 7) << 4)),
                  Bg0 + (size_t)((cc & 3) * 32 + k) * T_ + t0 + tc * 8);
        }
        CP_COMMIT();
    };
    bfill(0, 0);            // group includes A preload
    bfill(1, 1);
    bfill(2, 2);
    bfill(3, 3);

    const int gid = lid >> 2, qid = lid & 3;
    int wstg = 4, rstg = 0;
    #pragma unroll 1
    for (int cp = 0; cp < 16; cp += 2) {
        if (cp < 14) CP_WAIT(2); else CP_WAIT(0);    // stages cp, cp+1 complete
        __syncthreads();
        if (cp + 4 < 16) { bfill(wstg, cp + 4); if (++wstg == NSTG) wstg = 0; }
        if (cp + 5 < 16) { bfill(wstg, cp + 5); if (++wstg == NSTG) wstg = 0; }

        mma_chunk1(acc, sb + (uint32_t)((cp & 3) * 8192),
                   sb + L1_AB + (uint32_t)(rstg * 8192), warp_m, warp_n, lid);
        if (++rstg == NSTG) rstg = 0;
        mma_chunk1(acc, sb + (uint32_t)(((cp + 1) & 3) * 8192),
                   sb + L1_AB + (uint32_t)(rstg * 8192), warp_m, warp_n, lid);
        if (++rstg == NSTG) rstg = 0;

        if ((cp & 3) == 2) {
            // t-tile (cp+1)>>2 done: bias + gelu -> fp16, channel-shuffled store
            int t0 = (tb + ((cp + 1) >> 2)) * BN;
            #pragma unroll
            for (int mi = 0; mi < 2; mi++) {
                #pragma unroll
                for (int half = 0; half < 2; half++) {
                    int   m    = m0 + warp_m * 32 + mi * 16 + gid + half * 8;
                    float bias = b1[m];
                    int   cs   = ((m & 511) << 2) + g;
                    __half* orow = g_h + ((size_t)b * H_ + cs) * T_ + t0 + warp_n * 64;
                    #pragma unroll
                    for (int nj8 = 0; nj8 < 8; nj8++) {
                        float ox = gelu_tanh(acc[mi][nj8][half * 2 + 0] + bias);
                        float oy = gelu_tanh(acc[mi][nj8][half * 2 + 1] + bias);
                        *(__half2*)(orow + nj8 * 8 + qid * 2) = __float22half2_rn(make_float2(ox, oy));
                    }
                }
            }
            #pragma unroll
            for (int i = 0; i < 2; i++)
                #pragma unroll
                for (int j = 0; j < 8; j++)
                    #pragma unroll
                    for (int q = 0; q < 4; q++) acc[i][j][q] = 0.f;
        }
    }
}

// ---------------- layer 2: out = (W2 @ g_h + b2) * mask, pair-synced ----------------
__device__ __forceinline__ void prefetch2(uint32_t stg, const __half* Ag,
                                          const __half* Bg, int tid)
{
    #pragma unroll
    for (int it = 0; it < 2; it++) {
        int idx = it * 256 + tid;
        int m = idx >> 2, q = idx & 3;
        cpa16(stg + SA + swzb((uint32_t)(m * 64 + q * 16)), Ag + (size_t)m * 512 + q * 8);
    }
    #pragma unroll
    for (int it = 0; it < 2; it++) {
        int idx = it * 256 + tid;
        int k = idx >> 4, tc = idx & 15;
        cpa16(stg + SB + (uint32_t)(k * 256) + (((uint32_t)(tc * 16)) ^ ((uint32_t)(k & 7) << 4)),
              Bg + (size_t)k * T_ + tc * 8);
    }
    CP_COMMIT();
}

__global__ __launch_bounds__(256, 2)
void ffn_l2(const float* __restrict__ xm, const float* __restrict__ b2,
            float* __restrict__ out)
{
    extern __shared__ char smem[];
    const uint32_t sb = smem_to_u32(smem);
    const int tid = threadIdx.x, wid = tid >> 5, lid = tid & 31;
    const int warp_m = wid >> 1, warp_n = wid & 1;
    const int t0 = blockIdx.x * BN, m0 = blockIdx.y * BM, b = blockIdx.z;
    const int g2 = blockIdx.y;

    const __half* Ag = g_w2h + (size_t)m0 * 512;
    const __half* Bg = g_h + ((size_t)b * H_ + g2 * 512) * T_ + t0;
    const float* mrow = xm + (size_t)b * T_ + t0;

    float acc[2][8][4];
    #pragma unroll
    for (int i = 0; i < 2; i++)
        #pragma unroll
        for (int j = 0; j < 8; j++)
            #pragma unroll
            for (int q = 0; q < 4; q++) acc[i][j][q] = 0.f;

    int wstg = 0;
    for (int s = 0; s < 4; s++) {
        prefetch2(sb + wstg * STAGE, Ag + s * BK, Bg + (size_t)(s * BK) * T_, tid);
        if (++wstg == NSTG) wstg = 0;
    }
    int rstg = 0;
    #pragma unroll 1
    for (int cp = 0; cp < 16; cp += 2) {
        if (cp < 14) CP_WAIT(2); else CP_WAIT(0);
        __syncthreads();
        if (cp + 4 < 16) {
            prefetch2(sb + wstg * STAGE, Ag + (cp + 4) * BK, Bg + (size_t)((cp + 4) * BK) * T_, tid);
            if (++wstg == NSTG) wstg = 0;
        }
        if (cp + 5 < 16) {
            prefetch2(sb + wstg * STAGE, Ag + (cp + 5) * BK, Bg + (size_t)((cp + 5) * BK) * T_, tid);
            if (++wstg == NSTG) wstg = 0;
        }
        mma_chunk1(acc, sb + rstg * STAGE + SA, sb + rstg * STAGE + SB, warp_m, warp_n, lid);
        if (++rstg == NSTG) rstg = 0;
        mma_chunk1(acc, sb + rstg * STAGE + SA, sb + rstg * STAGE + SB, warp_m, warp_n, lid);
        if (++rstg == NSTG) rstg = 0;
    }

    const int gid = lid >> 2, qid = lid & 3;
    #pragma unroll
    for (int mi = 0; mi < 2; mi++) {
        #pragma unroll
        for (int half = 0; half < 2; half++) {
            int   m    = m0 + warp_m * 32 + mi * 16 + gid + half * 8;
            float bias = b2[m];
            float* orow = out + ((size_t)b * COUT + m) * T_ + t0 + warp_n * 64;
            const float* mr = mrow + warp_n * 64;
            #pragma unroll
            for (int nj8 = 0; nj8 < 8; nj8++) {
                float2 mk = *(const float2*)(mr + nj8 * 8 + qid * 2);
                float2 o;
                o.x = (acc[mi][nj8][half * 2 + 0] + bias) * mk.x;
                o.y = (acc[mi][nj8][half * 2 + 1] + bias) * mk.y;
                *(float2*)(orow + nj8 * 8 + qid * 2) = o;
            }
        }
    }
}

// ---------------- launch ----------------
extern "C" void kernel_launch(void* const* d_in, const int* in_sizes, int n_in,
                              void* d_out, int out_size)
{
    const float* x  = (const float*)d_in[0];
    const float* xm = (const float*)d_in[1];
    const float* w1 = (const float*)d_in[2];
    const float* b1 = (const float*)d_in[3];
    const float* w2 = (const float*)d_in[4];
    const float* b2 = (const float*)d_in[5];
    float* out = (float*)d_out;

    cudaFuncSetAttribute(ffn_l1, cudaFuncAttributeMaxDynamicSharedMemorySize, L1_SMEM);
    cudaFuncSetAttribute(ffn_l2, cudaFuncAttributeMaxDynamicSharedMemorySize, L2_SMEM);

    prep_all<<<16384 + 256, 256>>>(x, xm, w1, w2);

    dim3 g1(T_ / BN / TT, H_ / BM, B_);  // (4, 16, 16) = 1024 CTAs
    ffn_l1<<<g1, 256, L1_SMEM>>>(b1);

    dim3 g2(T_ / BN, COUT / BM, B_);     // (16, 4, 16) = 1024 CTAs
    ffn_l2<<<g2, 256, L2_SMEM>>>(xm, b2, out);
}

// round 14
// speedup vs baseline: 1.2520x; 1.0349x over previous
#include <cuda_runtime.h>
#include <cuda_fp16.h>
#include <cstdint>
#include <math.h>

// ---------------- problem constants ----------------
#define B_    16
#define CIN   512
#define T_    2048
#define H_    2048
#define COUT  512
#define G_    4

// ---------------- tiling: 4 CTAs/SM x 128 threads, CTA tile 64x128 ----------------
#define BM 64
#define BN 128
#define BK 32
#define TT 4               // t-tiles per l1 CTA (weight reuse)
#define NTHR 128

// ---------------- smem ----------------
// l1: A 4 planes x 4KB = 16KB + B ring 4 x 8KB = 32KB -> 48KB
// l2: ring 4 x (A 4KB + B 8KB) = 48KB
#define L1_AB    16384
#define L1_SMEM  (L1_AB + 4 * 8192)     // 49152
#define SA    0
#define SB    4096
#define STAGE 12288
#define NSTG  4
#define L2_SMEM (STAGE * NSTG)          // 49152

__device__ __forceinline__ uint32_t swzb(uint32_t o) {
    return o ^ ((o >> 2) & 0x30) ^ ((o >> 4) & 0x10);
}
__device__ __forceinline__ uint32_t rowsw(int row) {
    return (uint32_t)(((row & 3) << 4) ^ ((row & 4) << 2));
}

// ---------------- device scratch ----------------
__device__ __half g_w1h[(size_t)H_ * 128];
__device__ __half g_w2h[(size_t)COUT * 512];
__device__ __half g_xh[(size_t)B_ * CIN * T_];
__device__ __half g_h [(size_t)B_ * H_  * T_];

// ---------------- PTX helpers ----------------
__device__ __forceinline__ uint32_t smem_to_u32(const void* p) {
    uint32_t a;
    asm("{ .reg .u64 t; cvta.to.shared.u64 t, %1; cvt.u32.u64 %0, t; }" : "=r"(a) : "l"(p));
    return a;
}
__device__ __forceinline__ void ldsm4(uint32_t* r, uint32_t addr) {
    asm volatile("ldmatrix.sync.aligned.m8n8.x4.shared.b16 {%0,%1,%2,%3}, [%4];"
        : "=r"(r[0]), "=r"(r[1]), "=r"(r[2]), "=r"(r[3]) : "r"(addr));
}
__device__ __forceinline__ void ldsm4t(uint32_t* r, uint32_t addr) {
    asm volatile("ldmatrix.sync.aligned.m8n8.x4.trans.shared.b16 {%0,%1,%2,%3}, [%4];"
        : "=r"(r[0]), "=r"(r[1]), "=r"(r[2]), "=r"(r[3]) : "r"(addr));
}
__device__ __forceinline__ void mma16816(float* c, const uint32_t* a, uint32_t b0, uint32_t b1) {
    asm volatile("mma.sync.aligned.m16n8k16.row.col.f32.f16.f16.f32 "
        "{%0,%1,%2,%3}, {%4,%5,%6,%7}, {%8,%9}, {%0,%1,%2,%3};"
        : "+f"(c[0]), "+f"(c[1]), "+f"(c[2]), "+f"(c[3])
        : "r"(a[0]), "r"(a[1]), "r"(a[2]), "r"(a[3]), "r"(b0), "r"(b1));
}
__device__ __forceinline__ void cpa16(uint32_t dst, const __half* src) {
    asm volatile("cp.async.cg.shared.global [%0], [%1], 16;"
        :: "r"(dst), "l"(__cvta_generic_to_global(src)));
}
#define CP_COMMIT()  asm volatile("cp.async.commit_group;" ::: "memory")
#define CP_WAIT(n)   asm volatile("cp.async.wait_group %0;" :: "n"(n) : "memory")

__device__ __forceinline__ float gelu_tanh(float v) {
    float u = v * (0.7978845608028654f + 0.03567740814f * v * v);
    float t;
    asm("tanh.approx.f32 %0, %1;" : "=f"(t) : "f"(u));
    float w = 0.5f * v;
    return fmaf(w, t, w);
}

// ---------------- single prologue kernel ----------------
__global__ void prep_all(const float* __restrict__ x, const float* __restrict__ xm,
                         const float* __restrict__ w1, const float* __restrict__ w2)
{
    int bid = blockIdx.x;
    union { __half2 h[2]; uint2 u; } p;
    if (bid < 16384) {
        size_t i = (size_t)bid * 256 + threadIdx.x;
        size_t e = i * 4;
        int t = (int)(e & (T_ - 1));
        int b = (int)(e >> 20);
        float4 v = ((const float4*)x)[i];
        float4 mk = *(const float4*)(xm + (size_t)b * T_ + t);
        v.x *= mk.x; v.y *= mk.y; v.z *= mk.z; v.w *= mk.w;
        p.h[0] = __float22half2_rn(make_float2(v.x, v.y));
        p.h[1] = __float22half2_rn(make_float2(v.z, v.w));
        ((uint2*)g_xh)[i] = p.u;
    } else {
        int i = (bid - 16384) * 256 + threadIdx.x;
        float4 v = ((const float4*)w1)[i];
        p.h[0] = __float22half2_rn(make_float2(v.x, v.y));
        p.h[1] = __float22half2_rn(make_float2(v.z, v.w));
        ((uint2*)g_w1h)[i] = p.u;
        v = ((const float4*)w2)[i];
        p.h[0] = __float22half2_rn(make_float2(v.x, v.y));
        p.h[1] = __float22half2_rn(make_float2(v.z, v.w));
        ((uint2*)g_w2h)[i] = p.u;
    }
}

// ---------------- chunk body: 32x64 warp tile, 4 warps (2 wm x 2 wn) ----------------
__device__ __forceinline__ void mma_chunk1(float acc[2][8][4], uint32_t aBase, uint32_t bBase,
                                           int warp_m, int warp_n, int lid)
{
    const int rA = lid & 15;
    const int cA = (lid >> 4) << 4;
    const int kB = lid & 15;
    const uint32_t nbyte = (uint32_t)(warp_n * 128 + ((lid >> 4) << 4));

    #pragma unroll
    for (int k16 = 0; k16 < 2; k16++) {
        uint32_t aH[2][4];
        #pragma unroll
        for (int mi = 0; mi < 2; mi++) {
            int row = warp_m * 32 + mi * 16 + rA;
            uint32_t off = (uint32_t)(row * 64) + (((uint32_t)(k16 * 32 + cA)) ^ rowsw(row));
            ldsm4(aH[mi], aBase + off);
        }
        int krow = k16 * 16 + kB;
        uint32_t baddr = bBase + (uint32_t)(krow * 256);
        uint32_t bsw   = ((uint32_t)(krow & 7)) << 4;
        #pragma unroll
        for (int nj = 0; nj < 4; nj++) {
            uint32_t bT[4];
            ldsm4t(bT, baddr + ((nbyte + (uint32_t)(nj * 32)) ^ bsw));
            #pragma unroll
            for (int h = 0; h < 2; h++)
                #pragma unroll
                for (int mi = 0; mi < 2; mi++)
                    mma16816(acc[mi][nj * 2 + h], aH[mi], bT[h * 2], bT[h * 2 + 1]);
        }
    }
}

// ---------------- layer 1: A resident (16KB), B ring-4, pair-synced, TT=4 ----------------
__global__ __launch_bounds__(NTHR, 4)
void ffn_l1(const float* __restrict__ b1)
{
    extern __shared__ char smem[];
    const uint32_t sb = smem_to_u32(smem);
    const int tid = threadIdx.x, wid = tid >> 5, lid = tid & 31;
    const int warp_m = wid >> 1, warp_n = wid & 1;
    const int tb = blockIdx.x * TT;
    const int m0 = blockIdx.y * BM, b = blockIdx.z;
    const int g = m0 >> 9;                                  // 512 h-rows per group

    const __half* Ag = g_w1h + (size_t)m0 * 128;
    const __half* Bg0 = g_xh + ((size_t)b * CIN + g * 128) * T_;

    float acc[2][8][4];
    #pragma unroll
    for (int i = 0; i < 2; i++)
        #pragma unroll
        for (int j = 0; j < 8; j++)
            #pragma unroll
            for (int q = 0; q < 4; q++) acc[i][j][q] = 0.f;

    // preload all 4 A planes (64 rows x 64B each); rides in commit-group 0
    #pragma unroll
    for (int it = 0; it < 8; it++) {
        int idx = it * NTHR + tid;                          // 1024 x 16B
        int kk = idx >> 8, r = (idx & 255) >> 2, q = idx & 3;
        cpa16(sb + (uint32_t)(kk * 4096) + swzb((uint32_t)(r * 64 + q * 16)),
              Ag + (size_t)r * 128 + kk * 32 + q * 8);
    }
    // B chunk cc -> stage cc&3
    auto bfill = [&sb, &tb, &Bg0, &tid](int cc) {
        int stg = cc & 3;
        #pragma unroll
        for (int it = 0; it < 4; it++) {
            int idx = it * NTHR + tid;                      // 512 x 16B
            int k = idx >> 4, tc = idx & 15;
            int t0 = (tb + (cc >> 2)) * BN;
            cpa16(sb + L1_AB + (uint32_t)(stg * 8192) + (uint32_t)(k * 256) +
                      (((uint32_t)(tc * 16)) ^ ((uint32_t)(k & 7) << 4)),
                  Bg0 + (size_t)((cc & 3) * 32 + k) * T_ + t0 + tc * 8);
        }
        CP_COMMIT();
    };
    bfill(0);               // group 0 includes A preload
    bfill(1);

    const int gid = lid >> 2, qid = lid & 3;
    #pragma unroll 1
    for (int cp = 0; cp < 16; cp += 2) {
        CP_WAIT(0);                                         // stages cp, cp+1 (and A) ready
        __syncthreads();                                    // fences last iter's reads
        if (cp + 2 < 16) bfill(cp + 2);
        if (cp + 3 < 16) bfill(cp + 3);

        mma_chunk1(acc, sb + (uint32_t)((cp & 3) * 4096),
                   sb + L1_AB + (uint32_t)((cp & 3) * 8192), warp_m, warp_n, lid);
        mma_chunk1(acc, sb + (uint32_t)(((cp + 1) & 3) * 4096),
                   sb + L1_AB + (uint32_t)(((cp + 1) & 3) * 8192), warp_m, warp_n, lid);

        if ((cp & 3) == 2) {
            // t-tile (cp+1)>>2 done: bias + gelu -> fp16, channel-shuffled store
            int t0 = (tb + ((cp + 1) >> 2)) * BN;
            #pragma unroll
            for (int mi = 0; mi < 2; mi++) {
                #pragma unroll
                for (int half = 0; half < 2; half++) {
                    int   m    = m0 + warp_m * 32 + mi * 16 + gid + half * 8;
                    float bias = b1[m];
                    int   cs   = ((m & 511) << 2) + g;
                    __half* orow = g_h + ((size_t)b * H_ + cs) * T_ + t0 + warp_n * 64;
                    #pragma unroll
                    for (int nj8 = 0; nj8 < 8; nj8++) {
                        float ox = gelu_tanh(acc[mi][nj8][half * 2 + 0] + bias);
                        float oy = gelu_tanh(acc[mi][nj8][half * 2 + 1] + bias);
                        *(__half2*)(orow + nj8 * 8 + qid * 2) = __float22half2_rn(make_float2(ox, oy));
                    }
                }
            }
            #pragma unroll
            for (int i = 0; i < 2; i++)
                #pragma unroll
                for (int j = 0; j < 8; j++)
                    #pragma unroll
                    for (int q = 0; q < 4; q++) acc[i][j][q] = 0.f;
        }
    }
}

// ---------------- layer 2: ring-4 (A+B per stage), pair-synced ----------------
__device__ __forceinline__ void prefetch2(uint32_t sb, int cc, const __half* Ag,
                                          const __half* Bg, int tid)
{
    uint32_t stg = sb + (uint32_t)((cc & 3) * STAGE);
    #pragma unroll
    for (int it = 0; it < 2; it++) {
        int idx = it * NTHR + tid;                          // 256 x 16B (A: 64 rows)
        int m = idx >> 2, q = idx & 3;
        cpa16(stg + SA + swzb((uint32_t)(m * 64 + q * 16)),
              Ag + (size_t)m * 512 + cc * BK + q * 8);
    }
    #pragma unroll
    for (int it = 0; it < 4; it++) {
        int idx = it * NTHR + tid;                          // 512 x 16B (B)
        int k = idx >> 4, tc = idx & 15;
        cpa16(stg + SB + (uint32_t)(k * 256) + (((uint32_t)(tc * 16)) ^ ((uint32_t)(k & 7) << 4)),
              Bg + (size_t)(cc * BK + k) * T_ + tc * 8);
    }
    CP_COMMIT();
}

__global__ __launch_bounds__(NTHR, 4)
void ffn_l2(const float* __restrict__ xm, const float* __restrict__ b2,
            float* __restrict__ out)
{
    extern __shared__ char smem[];
    const uint32_t sb = smem_to_u32(smem);
    const int tid = threadIdx.x, wid = tid >> 5, lid = tid & 31;
    const int warp_m = wid >> 1, warp_n = wid & 1;
    const int t0 = blockIdx.x * BN, m0 = blockIdx.y * BM, b = blockIdx.z;
    const int g2 = m0 >> 7;                                 // 128 out-channels per group

    const __half* Ag = g_w2h + (size_t)m0 * 512;
    const __half* Bg = g_h + ((size_t)b * H_ + g2 * 512) * T_ + t0;
    const float* mrow = xm + (size_t)b * T_ + t0;

    float acc[2][8][4];
    #pragma unroll
    for (int i = 0; i < 2; i++)
        #pragma unroll
        for (int j = 0; j < 8; j++)
            #pragma unroll
            for (int q = 0; q < 4; q++) acc[i][j][q] = 0.f;

    prefetch2(sb, 0, Ag, Bg, tid);
    prefetch2(sb, 1, Ag, Bg, tid);

    #pragma unroll 1
    for (int cp = 0; cp < 16; cp += 2) {
        CP_WAIT(0);
        __syncthreads();
        if (cp + 2 < 16) prefetch2(sb, cp + 2, Ag, Bg, tid);
        if (cp + 3 < 16) prefetch2(sb, cp + 3, Ag, Bg, tid);

        mma_chunk1(acc, sb + (uint32_t)((cp & 3) * STAGE) + SA,
                   sb + (uint32_t)((cp & 3) * STAGE) + SB, warp_m, warp_n, lid);
        mma_chunk1(acc, sb + (uint32_t)(((cp + 1) & 3) * STAGE) + SA,
                   sb + (uint32_t)(((cp + 1) & 3) * STAGE) + SB, warp_m, warp_n, lid);
    }

    const int gid = lid >> 2, qid = lid & 3;
    #pragma unroll
    for (int mi = 0; mi < 2; mi++) {
        #pragma unroll
        for (int half = 0; half < 2; half++) {
            int   m    = m0 + warp_m * 32 + mi * 16 + gid + half * 8;
            float bias = b2[m];
            float* orow = out + ((size_t)b * COUT + m) * T_ + t0 + warp_n * 64;
            const float* mr = mrow + warp_n * 64;
            #pragma unroll
            for (int nj8 = 0; nj8 < 8; nj8++) {
                float2 mk = *(const float2*)(mr + nj8 * 8 + qid * 2);
                float2 o;
                o.x = (acc[mi][nj8][half * 2 + 0] + bias) * mk.x;
                o.y = (acc[mi][nj8][half * 2 + 1] + bias) * mk.y;
                *(float2*)(orow + nj8 * 8 + qid * 2) = o;
            }
        }
    }
}

// ---------------- launch ----------------
extern "C" void kernel_launch(void* const* d_in, const int* in_sizes, int n_in,
                              void* d_out, int out_size)
{
    const float* x  = (const float*)d_in[0];
    const float* xm = (const float*)d_in[1];
    const float* w1 = (const float*)d_in[2];
    const float* b1 = (const float*)d_in[3];
    const float* w2 = (const float*)d_in[4];
    const float* b2 = (const float*)d_in[5];
    float* out = (float*)d_out;

    cudaFuncSetAttribute(ffn_l1, cudaFuncAttributeMaxDynamicSharedMemorySize, L1_SMEM);
    cudaFuncSetAttribute(ffn_l2, cudaFuncAttributeMaxDynamicSharedMemorySize, L2_SMEM);

    prep_all<<<16384 + 256, 256>>>(x, xm, w1, w2);

    dim3 g1(T_ / BN / TT, H_ / BM, B_);   // (4, 32, 16) = 2048 CTAs
    ffn_l1<<<g1, NTHR, L1_SMEM>>>(b1);

    dim3 g2(T_ / BN, COUT / BM, B_);      // (16, 8, 16) = 2048 CTAs
    ffn_l2<<<g2, NTHR, L2_SMEM>>>(xm, b2, out);
}

// round 15
// speedup vs baseline: 1.2740x; 1.0176x over previous
#include <cuda_runtime.h>
#include <cuda_fp16.h>
#include <cstdint>
#include <math.h>

// ---------------- problem constants ----------------
#define B_    16
#define CIN   512
#define T_    2048
#define H_    2048
#define COUT  512
#define G_    4

// ---------------- tiling: 4 CTAs/SM x 128 threads, CTA tile 64x128 ----------------
#define BM 64
#define BN 128
#define BK 32
#define TT 4               // t-tiles per l1 CTA (weight reuse)
#define NTHR 128

// ---------------- smem ----------------
#define L1_AB    16384
#define L1_SMEM  (L1_AB + 4 * 8192)     // 49152
#define SA    0
#define SB    4096
#define STAGE 12288
#define NSTG  4
#define L2_SMEM (STAGE * NSTG)          // 49152

__device__ __forceinline__ uint32_t swzb(uint32_t o) {
    return o ^ ((o >> 2) & 0x30) ^ ((o >> 4) & 0x10);
}
__device__ __forceinline__ uint32_t rowsw(int row) {
    return (uint32_t)(((row & 3) << 4) ^ ((row & 4) << 2));
}

// ---------------- device scratch ----------------
__device__ __half g_w1h[(size_t)H_ * 128];
__device__ __half g_w2h[(size_t)COUT * 512];
__device__ __half g_xh[(size_t)B_ * CIN * T_];
__device__ __half g_h [(size_t)B_ * H_  * T_];

// ---------------- PTX helpers ----------------
__device__ __forceinline__ uint32_t smem_to_u32(const void* p) {
    uint32_t a;
    asm("{ .reg .u64 t; cvta.to.shared.u64 t, %1; cvt.u32.u64 %0, t; }" : "=r"(a) : "l"(p));
    return a;
}
__device__ __forceinline__ void ldsm4(uint32_t* r, uint32_t addr) {
    asm volatile("ldmatrix.sync.aligned.m8n8.x4.shared.b16 {%0,%1,%2,%3}, [%4];"
        : "=r"(r[0]), "=r"(r[1]), "=r"(r[2]), "=r"(r[3]) : "r"(addr));
}
__device__ __forceinline__ void ldsm4t(uint32_t* r, uint32_t addr) {
    asm volatile("ldmatrix.sync.aligned.m8n8.x4.trans.shared.b16 {%0,%1,%2,%3}, [%4];"
        : "=r"(r[0]), "=r"(r[1]), "=r"(r[2]), "=r"(r[3]) : "r"(addr));
}
__device__ __forceinline__ void mma16816(float* c, const uint32_t* a, uint32_t b0, uint32_t b1) {
    asm volatile("mma.sync.aligned.m16n8k16.row.col.f32.f16.f16.f32 "
        "{%0,%1,%2,%3}, {%4,%5,%6,%7}, {%8,%9}, {%0,%1,%2,%3};"
        : "+f"(c[0]), "+f"(c[1]), "+f"(c[2]), "+f"(c[3])
        : "r"(a[0]), "r"(a[1]), "r"(a[2]), "r"(a[3]), "r"(b0), "r"(b1));
}
__device__ __forceinline__ void cpa16(uint32_t dst, const __half* src) {
    asm volatile("cp.async.cg.shared.global [%0], [%1], 16;"
        :: "r"(dst), "l"(__cvta_generic_to_global(src)));
}
#define CP_COMMIT()  asm volatile("cp.async.commit_group;" ::: "memory")
#define CP_WAIT(n)   asm volatile("cp.async.wait_group %0;" :: "n"(n) : "memory")

__device__ __forceinline__ float gelu_tanh(float v) {
    float u = v * (0.7978845608028654f + 0.03567740814f * v * v);
    float t;
    asm("tanh.approx.f32 %0, %1;" : "=f"(t) : "f"(u));
    float w = 0.5f * v;
    return fmaf(w, t, w);
}

// ---------------- single prologue kernel (2 float4/thread, streaming x) ----------------
__global__ void prep_all(const float* __restrict__ x, const float* __restrict__ xm,
                         const float* __restrict__ w1, const float* __restrict__ w2)
{
    int bid = blockIdx.x;
    union { __half2 h[2]; uint2 u; } p;
    if (bid < 8192) {
        #pragma unroll
        for (int j = 0; j < 2; j++) {
            size_t i = (size_t)bid * 512 + j * 256 + threadIdx.x;
            size_t e = i * 4;
            int t = (int)(e & (T_ - 1));
            int b = (int)(e >> 20);
            float4 v = __ldcs((const float4*)x + i);
            float4 mk = *(const float4*)(xm + (size_t)b * T_ + t);
            v.x *= mk.x; v.y *= mk.y; v.z *= mk.z; v.w *= mk.w;
            p.h[0] = __float22half2_rn(make_float2(v.x, v.y));
            p.h[1] = __float22half2_rn(make_float2(v.z, v.w));
            ((uint2*)g_xh)[i] = p.u;
        }
    } else {
        int i = (bid - 8192) * 256 + threadIdx.x;
        float4 v = ((const float4*)w1)[i];
        p.h[0] = __float22half2_rn(make_float2(v.x, v.y));
        p.h[1] = __float22half2_rn(make_float2(v.z, v.w));
        ((uint2*)g_w1h)[i] = p.u;
        v = ((const float4*)w2)[i];
        p.h[0] = __float22half2_rn(make_float2(v.x, v.y));
        p.h[1] = __float22half2_rn(make_float2(v.z, v.w));
        ((uint2*)g_w2h)[i] = p.u;
    }
}

// ---------------- chunk body: batched loads (12 ldsm) then dense 32-MMA burst ----------------
__device__ __forceinline__ void mma_chunk1(float acc[2][8][4], uint32_t aBase, uint32_t bBase,
                                           int warp_m, int warp_n, int lid)
{
    const int rA = lid & 15;
    const int cA = (lid >> 4) << 4;
    const int kB = lid & 15;
    const uint32_t nbyte = (uint32_t)(warp_n * 128 + ((lid >> 4) << 4));

    uint32_t aF[2][2][4];     // [k16][mi]
    uint32_t bF[2][4][4];     // [k16][nj]

    #pragma unroll
    for (int k16 = 0; k16 < 2; k16++) {
        #pragma unroll
        for (int mi = 0; mi < 2; mi++) {
            int row = warp_m * 32 + mi * 16 + rA;
            uint32_t off = (uint32_t)(row * 64) + (((uint32_t)(k16 * 32 + cA)) ^ rowsw(row));
            ldsm4(aF[k16][mi], aBase + off);
        }
        int krow = k16 * 16 + kB;
        uint32_t baddr = bBase + (uint32_t)(krow * 256);
        uint32_t bsw   = ((uint32_t)(krow & 7)) << 4;
        #pragma unroll
        for (int nj = 0; nj < 4; nj++)
            ldsm4t(bF[k16][nj], baddr + ((nbyte + (uint32_t)(nj * 32)) ^ bsw));
    }
    #pragma unroll
    for (int k16 = 0; k16 < 2; k16++)
        #pragma unroll
        for (int nj = 0; nj < 4; nj++)
            #pragma unroll
            for (int h = 0; h < 2; h++)
                #pragma unroll
                for (int mi = 0; mi < 2; mi++)
                    mma16816(acc[mi][nj * 2 + h], aF[k16][mi],
                             bF[k16][nj][h * 2], bF[k16][nj][h * 2 + 1]);
}

// ---------------- layer 1: A resident (16KB), B ring-4, pair-synced, TT=4 ----------------
__global__ __launch_bounds__(NTHR, 4)
void ffn_l1(const float* __restrict__ b1)
{
    extern __shared__ char smem[];
    const uint32_t sb = smem_to_u32(smem);
    const int tid = threadIdx.x, wid = tid >> 5, lid = tid & 31;
    const int warp_m = wid >> 1, warp_n = wid & 1;
    const int tb = blockIdx.x * TT;
    const int m0 = blockIdx.y * BM, b = blockIdx.z;
    const int g = m0 >> 9;

    const __half* Ag = g_w1h + (size_t)m0 * 128;
    const __half* Bg0 = g_xh + ((size_t)b * CIN + g * 128) * T_;

    float acc[2][8][4];
    #pragma unroll
    for (int i = 0; i < 2; i++)
        #pragma unroll
        for (int j = 0; j < 8; j++)
            #pragma unroll
            for (int q = 0; q < 4; q++) acc[i][j][q] = 0.f;

    // preload all 4 A planes (64 rows x 64B each); rides in commit-group 0
    #pragma unroll
    for (int it = 0; it < 8; it++) {
        int idx = it * NTHR + tid;
        int kk = idx >> 8, r = (idx & 255) >> 2, q = idx & 3;
        cpa16(sb + (uint32_t)(kk * 4096) + swzb((uint32_t)(r * 64 + q * 16)),
              Ag + (size_t)r * 128 + kk * 32 + q * 8);
    }
    auto bfill = [&sb, &tb, &Bg0, &tid](int cc) {
        int stg = cc & 3;
        #pragma unroll
        for (int it = 0; it < 4; it++) {
            int idx = it * NTHR + tid;
            int k = idx >> 4, tc = idx & 15;
            int t0 = (tb + (cc >> 2)) * BN;
            cpa16(sb + L1_AB + (uint32_t)(stg * 8192) + (uint32_t)(k * 256) +
                      (((uint32_t)(tc * 16)) ^ ((uint32_t)(k & 7) << 4)),
                  Bg0 + (size_t)((cc & 3) * 32 + k) * T_ + t0 + tc * 8);
        }
        CP_COMMIT();
    };
    bfill(0);
    bfill(1);

    const int gid = lid >> 2, qid = lid & 3;
    #pragma unroll 1
    for (int cp = 0; cp < 16; cp += 2) {
        CP_WAIT(0);
        __syncthreads();
        if (cp + 2 < 16) bfill(cp + 2);
        if (cp + 3 < 16) bfill(cp + 3);

        mma_chunk1(acc, sb + (uint32_t)((cp & 3) * 4096),
                   sb + L1_AB + (uint32_t)((cp & 3) * 8192), warp_m, warp_n, lid);
        mma_chunk1(acc, sb + (uint32_t)(((cp + 1) & 3) * 4096),
                   sb + L1_AB + (uint32_t)(((cp + 1) & 3) * 8192), warp_m, warp_n, lid);

        if ((cp & 3) == 2) {
            int t0 = (tb + ((cp + 1) >> 2)) * BN;
            #pragma unroll
            for (int mi = 0; mi < 2; mi++) {
                #pragma unroll
                for (int half = 0; half < 2; half++) {
                    int   m    = m0 + warp_m * 32 + mi * 16 + gid + half * 8;
                    float bias = b1[m];
                    int   cs   = ((m & 511) << 2) + g;
                    __half* orow = g_h + ((size_t)b * H_ + cs) * T_ + t0 + warp_n * 64;
                    #pragma unroll
                    for (int nj8 = 0; nj8 < 8; nj8++) {
                        float ox = gelu_tanh(acc[mi][nj8][half * 2 + 0] + bias);
                        float oy = gelu_tanh(acc[mi][nj8][half * 2 + 1] + bias);
                        *(__half2*)(orow + nj8 * 8 + qid * 2) = __float22half2_rn(make_float2(ox, oy));
                    }
                }
            }
            #pragma unroll
            for (int i = 0; i < 2; i++)
                #pragma unroll
                for (int j = 0; j < 8; j++)
                    #pragma unroll
                    for (int q = 0; q < 4; q++) acc[i][j][q] = 0.f;
        }
    }
}

// ---------------- layer 2: ring-4 (A+B per stage), pair-synced ----------------
__device__ __forceinline__ void prefetch2(uint32_t sb, int cc, const __half* Ag,
                                          const __half* Bg, int tid)
{
    uint32_t stg = sb + (uint32_t)((cc & 3) * STAGE);
    #pragma unroll
    for (int it = 0; it < 2; it++) {
        int idx = it * NTHR + tid;
        int m = idx >> 2, q = idx & 3;
        cpa16(stg + SA + swzb((uint32_t)(m * 64 + q * 16)),
              Ag + (size_t)m * 512 + cc * BK + q * 8);
    }
    #pragma unroll
    for (int it = 0; it < 4; it++) {
        int idx = it * NTHR + tid;
        int k = idx >> 4, tc = idx & 15;
        cpa16(stg + SB + (uint32_t)(k * 256) + (((uint32_t)(tc * 16)) ^ ((uint32_t)(k & 7) << 4)),
              Bg + (size_t)(cc * BK + k) * T_ + tc * 8);
    }
    CP_COMMIT();
}

__global__ __launch_bounds__(NTHR, 4)
void ffn_l2(const float* __restrict__ xm, const float* __restrict__ b2,
            float* __restrict__ out)
{
    extern __shared__ char smem[];
    const uint32_t sb = smem_to_u32(smem);
    const int tid = threadIdx.x, wid = tid >> 5, lid = tid & 31;
    const int warp_m = wid >> 1, warp_n = wid & 1;
    const int t0 = blockIdx.x * BN, m0 = blockIdx.y * BM, b = blockIdx.z;
    const int g2 = m0 >> 7;

    const __half* Ag = g_w2h + (size_t)m0 * 512;
    const __half* Bg = g_h + ((size_t)b * H_ + g2 * 512) * T_ + t0;
    const float* mrow = xm + (size_t)b * T_ + t0;

    float acc[2][8][4];
    #pragma unroll
    for (int i = 0; i < 2; i++)
        #pragma unroll
        for (int j = 0; j < 8; j++)
            #pragma unroll
            for (int q = 0; q < 4; q++) acc[i][j][q] = 0.f;

    prefetch2(sb, 0, Ag, Bg, tid);
    prefetch2(sb, 1, Ag, Bg, tid);

    #pragma unroll 1
    for (int cp = 0; cp < 16; cp += 2) {
        CP_WAIT(0);
        __syncthreads();
        if (cp + 2 < 16) prefetch2(sb, cp + 2, Ag, Bg, tid);
        if (cp + 3 < 16) prefetch2(sb, cp + 3, Ag, Bg, tid);

        mma_chunk1(acc, sb + (uint32_t)((cp & 3) * STAGE) + SA,
                   sb + (uint32_t)((cp & 3) * STAGE) + SB, warp_m, warp_n, lid);
        mma_chunk1(acc, sb + (uint32_t)(((cp + 1) & 3) * STAGE) + SA,
                   sb + (uint32_t)(((cp + 1) & 3) * STAGE) + SB, warp_m, warp_n, lid);
    }

    const int gid = lid >> 2, qid = lid & 3;
    #pragma unroll
    for (int mi = 0; mi < 2; mi++) {
        #pragma unroll
        for (int half = 0; half < 2; half++) {
            int   m    = m0 + warp_m * 32 + mi * 16 + gid + half * 8;
            float bias = b2[m];
            float* orow = out + ((size_t)b * COUT + m) * T_ + t0 + warp_n * 64;
            const float* mr = mrow + warp_n * 64;
            #pragma unroll
            for (int nj8 = 0; nj8 < 8; nj8++) {
                float2 mk = *(const float2*)(mr + nj8 * 8 + qid * 2);
                float2 o;
                o.x = (acc[mi][nj8][half * 2 + 0] + bias) * mk.x;
                o.y = (acc[mi][nj8][half * 2 + 1] + bias) * mk.y;
                *(float2*)(orow + nj8 * 8 + qid * 2) = o;
            }
        }
    }
}

// ---------------- launch ----------------
extern "C" void kernel_launch(void* const* d_in, const int* in_sizes, int n_in,
                              void* d_out, int out_size)
{
    const float* x  = (const float*)d_in[0];
    const float* xm = (const float*)d_in[1];
    const float* w1 = (const float*)d_in[2];
    const float* b1 = (const float*)d_in[3];
    const float* w2 = (const float*)d_in[4];
    const float* b2 = (const float*)d_in[5];
    float* out = (float*)d_out;

    cudaFuncSetAttribute(ffn_l1, cudaFuncAttributeMaxDynamicSharedMemorySize, L1_SMEM);
    cudaFuncSetAttribute(ffn_l2, cudaFuncAttributeMaxDynamicSharedMemorySize, L2_SMEM);

    prep_all<<<8192 + 256, 256>>>(x, xm, w1, w2);

    dim3 g1(T_ / BN / TT, H_ / BM, B_);   // (4, 32, 16) = 2048 CTAs
    ffn_l1<<<g1, NTHR, L1_SMEM>>>(b1);

    dim3 g2(T_ / BN, COUT / BM, B_);      // (16, 8, 16) = 2048 CTAs
    ffn_l2<<<g2, NTHR, L2_SMEM>>>(xm, b2, out);
}